// round 15
// baseline (speedup 1.0000x reference)
#include <cuda_runtime.h>
#include <cuda_bf16.h>
#include <cstdint>

// Problem constants
#define Bq 32
#define Tq 576
#define Cq 1024
#define Hq 16
#define Dq 64
#define Mq (Bq * Tq)          // 18432
#define N_QKV (3 * Cq)        // 3072

// Scratch (device globals; no allocation allowed)
__device__ float g_Q[(size_t)Bq * Hq * Tq * Dq];   // [B,H,T,D], tf32-rounded
__device__ float g_K[(size_t)Bq * Hq * Tq * Dq];
__device__ float g_V[(size_t)Bq * Hq * Tq * Dq];
__device__ float g_Y[(size_t)Mq * Cq];             // attention out, PACKED-A layout
__device__ float g_Atf[(size_t)Mq * Cq];           // emb tf32, PACKED-A layout
__device__ float g_WqkvT[(size_t)N_QKV * Cq];      // PACKED-B layout
__device__ float g_WprojT[(size_t)Cq * Cq];        // PACKED-B layout

// ---------------------------------------------------------------------------
// Fragment-packed layouts (K = 1024 -> 32 k-blocks of 32); see round 9.
// packA float4 view: Af4[(mblk*32+kblk)*1024 + ((m16)*4+ks)*32 + lid]
// packB float2 view: Bf2[(nblk128*32+kblk)*2048 + (nt*4+ks)*32 + lid]
// ---------------------------------------------------------------------------
__device__ __forceinline__ size_t packA_idx(int m, int k) {
  const int mblk = m >> 7, kblk = k >> 5;
  const int mt = (m >> 4) & 7, ks = (k >> 3) & 3;
  const int g = m & 7, mh = (m >> 3) & 1;
  const int tig = k & 3, kh = (k >> 2) & 1;
  return ((((size_t)(mblk * 32 + kblk) * 8 + mt) * 4 + ks) * 32 + (g * 4 + tig)) * 4
         + (mh + 2 * kh);
}

__device__ __forceinline__ size_t packB_idx(int n, int k) {
  const int nblk = n >> 7, kblk = k >> 5;
  const int nt = (n >> 3) & 15, ks = (k >> 3) & 3;
  const int g = n & 7;
  const int tig = k & 3, kh = (k >> 2) & 1;
  return ((((size_t)(nblk * 32 + kblk) * 16 + nt) * 4 + ks) * 32 + (g * 4 + tig)) * 2
         + kh;
}

// ---------------------------------------------------------------------------
__device__ __forceinline__ float f2tf32(float x) {
  uint32_t r;
  asm("cvt.rna.tf32.f32 %0, %1;" : "=r"(r) : "f"(x));
  return __uint_as_float(r);
}

__device__ __forceinline__ void cp_async16(uint32_t saddr, const void* gaddr) {
  asm volatile("cp.async.cg.shared.global [%0], [%1], 16;" :: "r"(saddr), "l"(gaddr));
}
#define CP_COMMIT() asm volatile("cp.async.commit_group;" ::: "memory")
#define CP_WAIT(n)  asm volatile("cp.async.wait_group %0;" :: "n"(n) : "memory")

__device__ __forceinline__ uint32_t smem_u32(const void* p) {
  uint32_t a;
  asm("{ .reg .u64 t; cvta.to.shared.u64 t, %1; cvt.u32.u64 %0, t; }"
      : "=r"(a) : "l"(p));
  return a;
}

__device__ __forceinline__ void prefetch_l1(const void* p) {
  asm volatile("prefetch.global.L1 [%0];" :: "l"(p));
}

__device__ __forceinline__ void mma_tf32(float* c, const uint32_t* a, const uint32_t* b) {
  asm volatile(
      "mma.sync.aligned.m16n8k8.row.col.f32.tf32.tf32.f32 "
      "{%0,%1,%2,%3}, {%4,%5,%6,%7}, {%8,%9}, {%0,%1,%2,%3};"
      : "+f"(c[0]), "+f"(c[1]), "+f"(c[2]), "+f"(c[3])
      : "r"(a[0]), "r"(a[1]), "r"(a[2]), "r"(a[3]), "r"(b[0]), "r"(b[1]));
}

__device__ __forceinline__ void mma_tf32_2(float* c, const uint32_t* a,
                                           uint32_t b0, uint32_t b1) {
  asm volatile(
      "mma.sync.aligned.m16n8k8.row.col.f32.tf32.tf32.f32 "
      "{%0,%1,%2,%3}, {%4,%5,%6,%7}, {%8,%9}, {%0,%1,%2,%3};"
      : "+f"(c[0]), "+f"(c[1]), "+f"(c[2]), "+f"(c[3])
      : "r"(a[0]), "r"(a[1]), "r"(a[2]), "r"(a[3]), "r"(b0), "r"(b1));
}

// ---------------------------------------------------------------------------
// emb -> tf32-rounded, packed-A layout
// ---------------------------------------------------------------------------
__global__ __launch_bounds__(256) void round_pack_kernel(const float* __restrict__ src,
                                                         float* __restrict__ dst) {
  const int i = blockIdx.x * 256 + threadIdx.x;
  if (i < Mq * Cq / 4) {
    const int m = (i * 4) / Cq;
    const int k = (i * 4) % Cq;
    const float4 v = ((const float4*)src)[i];
    dst[packA_idx(m, k + 0)] = f2tf32(v.x);
    dst[packA_idx(m, k + 1)] = f2tf32(v.y);
    dst[packA_idx(m, k + 2)] = f2tf32(v.z);
    dst[packA_idx(m, k + 3)] = f2tf32(v.w);
  }
}

// ---------------------------------------------------------------------------
// Weight transpose + tf32 + packed-B: dst_packedB[n][k] = tf32(src[k][n])
// ---------------------------------------------------------------------------
__global__ __launch_bounds__(256) void transpose_pack_kernel(
    const float* __restrict__ src, float* __restrict__ dst, int C) {
  __shared__ float t[32][33];
  const int c0 = blockIdx.x * 32, r0 = blockIdx.y * 32;
  const int x = threadIdx.x, y = threadIdx.y;   // 32 x 8
#pragma unroll
  for (int i = 0; i < 32; i += 8)
    t[y + i][x] = src[(size_t)(r0 + y + i) * C + c0 + x];
  __syncthreads();
#pragma unroll
  for (int i = 0; i < 32; i += 8)
    dst[packB_idx(c0 + y + i, r0 + x)] = f2tf32(t[x][y + i]);
}

// ---------------------------------------------------------------------------
// tf32 mma.sync GEMM on packed operands, CTA tile 128x256 (512 thr, 16 warps
// = 2m x 8n, warp 64x32). Fragments streamed via __ldg; register prefetch
// depth 1 + full-warp L1 prefetch depth 2; ONE __syncthreads per k-tile to
// bound warp drift so intra-CTA line sharing actually lands in L1 (cuts L2
// traffic to the theoretical 1.5 MB/CTA).
// MODE 0: QKV scatter epilogue; MODE 1: plain store.
// ---------------------------------------------------------------------------
#define G_NK 32

#define LOADG(kt_, ks_, c_) do {                                               \
    _Pragma("unroll")                                                          \
    for (int mt_ = 0; mt_ < 4; mt_++)                                          \
      af[c_][mt_] = __ldg(Afw + (kt_) * 1024 + (mt_ * 4 + (ks_)) * 32);        \
    _Pragma("unroll")                                                          \
    for (int nt_ = 0; nt_ < 4; nt_++)                                          \
      bf[c_][nt_] = __ldg(Bfw + (kt_) * 2048 + (nt_ * 4 + (ks_)) * 32);        \
  } while (0)

#define PREFG(kt_, ks_) do {                                                   \
    _Pragma("unroll")                                                          \
    for (int mt_ = 0; mt_ < 4; mt_++)                                          \
      prefetch_l1(Afw + (kt_) * 1024 + (mt_ * 4 + (ks_)) * 32);                \
    _Pragma("unroll")                                                          \
    for (int nt_ = 0; nt_ < 4; nt_++)                                          \
      prefetch_l1(Bfw + (kt_) * 2048 + (nt_ * 4 + (ks_)) * 32);                \
  } while (0)

template <int MODE>
__global__ __launch_bounds__(512, 1) void tc_gemm_kernel(
    const float* __restrict__ A, const float* __restrict__ BT,
    const float* __restrict__ bias, float* __restrict__ Out) {
  const int tid = threadIdx.x;
  const int wid = tid >> 5;
  const int lid = tid & 31;
  const int mblk = blockIdx.y;
  const int nblk = blockIdx.x;          // 256-wide tile index
  const int m0 = mblk * 128;
  const int n0 = nblk * 256;
  const int warp_m = wid & 1;           // 0..1
  const int warp_n = wid >> 1;          // 0..7
  const int g = lid >> 2, tig = lid & 3;

  // A: per-warp fragment base (128-row packA block mblk).
  const float4* Afw = (const float4*)A + (size_t)mblk * 32768 + warp_m * 512 + lid;
  // B: 256-wide tile spans two 128-col packB blocks; warp_n>=4 takes the odd one.
  const float2* Bfw = (const float2*)BT
      + (size_t)(nblk * 2 + (warp_n >> 2)) * 65536 + (warp_n & 3) * 512 + lid;

  float acc[4][4][4];
#pragma unroll
  for (int i = 0; i < 4; i++)
#pragma unroll
    for (int j = 0; j < 4; j++)
#pragma unroll
      for (int q = 0; q < 4; q++) acc[i][j][q] = 0.f;

  float4 af[2][4];
  float2 bf[2][4];

  LOADG(0, 0, 0);
  PREFG(0, 1);
  for (int kt = 0; kt < G_NK; kt++) {
    if (kt) __syncthreads();   // bound warp drift to <=1 k-tile (L1 reuse)
#pragma unroll
    for (int ks = 0; ks < 4; ks++) {
      const int step = kt * 4 + ks;
      const int c = step & 1;
      const int nstep = step + 1;
      if (nstep < G_NK * 4) LOADG(nstep >> 2, nstep & 3, c ^ 1);
      const int pstep = step + 2;
      if (pstep < G_NK * 4) PREFG(pstep >> 2, pstep & 3);
#pragma unroll
      for (int mt = 0; mt < 4; mt++)
#pragma unroll
        for (int nt = 0; nt < 4; nt++)
          mma_tf32(acc[mt][nt], (const uint32_t*)&af[c][mt],
                   (const uint32_t*)&bf[c][nt]);
    }
  }

  // Epilogue (same fragment->logical mapping as rounds 4-14)
#pragma unroll
  for (int mt = 0; mt < 4; mt++) {
    const int row0 = m0 + warp_m * 64 + mt * 16 + g;
#pragma unroll
    for (int half = 0; half < 2; half++) {
      const int m = row0 + half * 8;
      const int bb = m / Tq;
      const int t = m % Tq;
#pragma unroll
      for (int nt = 0; nt < 4; nt++) {
        const int n = n0 + warp_n * 32 + nt * 8 + tig * 2;
        const float2 bv = *(const float2*)&bias[n];
        float2 o;
        o.x = acc[mt][nt][half * 2 + 0] + bv.x;
        o.y = acc[mt][nt][half * 2 + 1] + bv.y;
        if (MODE == 0) {
          o.x = f2tf32(o.x);
          o.y = f2tf32(o.y);
          const int which = n >> 10;
          const int ccn = n & 1023;
          const int h = ccn >> 6;
          const int d = ccn & 63;
          float* dst = (which == 0) ? g_Q : (which == 1) ? g_K : g_V;
          *(float2*)(dst + ((size_t)(bb * Hq + h) * Tq + t) * Dq + d) = o;
        } else {
          *(float2*)(Out + (size_t)m * Cq + n) = o;
        }
      }
    }
  }
}

// ---------------------------------------------------------------------------
// Tensor-core causal flash attention (round 5 core; epilogue writes packed-A Y).
// ---------------------------------------------------------------------------
#define QT 64
#define KST 68
#define VST 72
#define PST 68
#define KBUF (64 * KST)
#define VBUF (64 * VST)
#define ATTN_SMEM ((2 * KBUF + 2 * VBUF + 64 * PST) * 4)   // 89088 B

__device__ __forceinline__ void attn_prefetch(const float* Kg, const float* Vg,
                                              float* Ksb, float* Vsb, int tid) {
#pragma unroll
  for (int i = 0; i < 8; i++) {
    const int c = tid + i * 128;
    const int r = c >> 4;
    const int c4 = (c & 15) * 4;
    cp_async16(smem_u32(Ksb + r * KST + c4), Kg + (size_t)r * Dq + c4);
    cp_async16(smem_u32(Vsb + r * VST + c4), Vg + (size_t)r * Dq + c4);
  }
  CP_COMMIT();
}

__global__ __launch_bounds__(128) void flash_attn_tc_kernel() {
  const int bh = blockIdx.x;
  const int qt = blockIdx.y;
  const int b = bh / Hq;
  const int h = bh % Hq;

  const float* Qb = g_Q + (size_t)bh * Tq * Dq;
  const float* Kb = g_K + (size_t)bh * Tq * Dq;
  const float* Vb = g_V + (size_t)bh * Tq * Dq;

  extern __shared__ float smf[];
  float* KsA = smf;
  float* VsA = smf + 2 * KBUF;
  float* Ps  = smf + 2 * KBUF + 2 * VBUF;

  const int tid = threadIdx.x;
  const int wid = tid >> 5;
  const int lid = tid & 31;
  const int g = lid >> 2;
  const int tig = lid & 3;
  const int q0 = qt * QT;
  const int nkt = qt + 1;

  attn_prefetch(Kb, Vb, KsA, VsA, tid);

  {
#pragma unroll
    for (int i = 0; i < 8; i++) {
      const int c = tid + i * 128;
      const int r = c >> 4;
      const int c4 = (c & 15) * 4;
      const float4 v = *(const float4*)&Qb[(size_t)(q0 + r) * Dq + c4];
      float* dr = &Ps[r * PST + c4];
      dr[0] = v.x; dr[1] = v.y; dr[2] = v.z; dr[3] = v.w;
    }
  }
  __syncthreads();

  uint32_t qa[8][4];
  {
    const uint32_t* Qsm = (const uint32_t*)Ps;
    const int r0 = 16 * wid + g;
#pragma unroll
    for (int ks = 0; ks < 8; ks++) {
      const int kb = 8 * ks + tig;
      qa[ks][0] = Qsm[r0 * PST + kb];
      qa[ks][1] = Qsm[(r0 + 8) * PST + kb];
      qa[ks][2] = Qsm[r0 * PST + kb + 4];
      qa[ks][3] = Qsm[(r0 + 8) * PST + kb + 4];
    }
  }

  float o[8][4];
#pragma unroll
  for (int i = 0; i < 8; i++)
#pragma unroll
    for (int j = 0; j < 4; j++) o[i][j] = 0.f;
  float m0r = -1e30f, m1r = -1e30f, l0 = 0.f, l1 = 0.f;
  const float scale = 1.0f / 64.0f;
  const int myrow0 = 16 * wid + g;
  const int myrow1 = myrow0 + 8;

  for (int kt = 0; kt < nkt; kt++) {
    const int buf = kt & 1;
    __syncthreads();
    if (kt + 1 < nkt) {
      attn_prefetch(Kb + (size_t)(kt + 1) * 64 * Dq, Vb + (size_t)(kt + 1) * 64 * Dq,
                    KsA + (buf ^ 1) * KBUF, VsA + (buf ^ 1) * VBUF, tid);
      CP_WAIT(1);
    } else {
      CP_WAIT(0);
    }
    __syncthreads();

    const uint32_t* Ksm = (const uint32_t*)(KsA + buf * KBUF);
    float s[8][4];
#pragma unroll
    for (int nt = 0; nt < 8; nt++) {
      s[nt][0] = s[nt][1] = s[nt][2] = s[nt][3] = 0.f;
      const uint32_t* kr = Ksm + (8 * nt + g) * KST;
#pragma unroll
      for (int ks = 0; ks < 8; ks++) {
        const int kb = 8 * ks + tig;
        mma_tf32_2(s[nt], qa[ks], kr[kb], kr[kb + 4]);
      }
    }

    const bool diag = (kt == qt);
    float mx0 = -1e30f, mx1 = -1e30f;
#pragma unroll
    for (int nt = 0; nt < 8; nt++) {
#pragma unroll
      for (int ccx = 0; ccx < 2; ccx++) {
        const int kcol = 8 * nt + 2 * tig + ccx;
        const bool ok0 = !diag || (kcol <= myrow0);
        const bool ok1 = !diag || (kcol <= myrow1);
        s[nt][ccx]     = ok0 ? s[nt][ccx] * scale     : -1e30f;
        s[nt][2 + ccx] = ok1 ? s[nt][2 + ccx] * scale : -1e30f;
        mx0 = fmaxf(mx0, s[nt][ccx]);
        mx1 = fmaxf(mx1, s[nt][2 + ccx]);
      }
    }
    mx0 = fmaxf(mx0, __shfl_xor_sync(0xffffffffu, mx0, 1));
    mx0 = fmaxf(mx0, __shfl_xor_sync(0xffffffffu, mx0, 2));
    mx1 = fmaxf(mx1, __shfl_xor_sync(0xffffffffu, mx1, 1));
    mx1 = fmaxf(mx1, __shfl_xor_sync(0xffffffffu, mx1, 2));

    const float nm0 = fmaxf(m0r, mx0);
    const float nm1 = fmaxf(m1r, mx1);
    const float c0 = __expf(m0r - nm0);
    const float c1 = __expf(m1r - nm1);

    float ps0 = 0.f, ps1 = 0.f;
#pragma unroll
    for (int nt = 0; nt < 8; nt++) {
      const float p00 = __expf(s[nt][0] - nm0);
      const float p01 = __expf(s[nt][1] - nm0);
      const float p10 = __expf(s[nt][2] - nm1);
      const float p11 = __expf(s[nt][3] - nm1);
      ps0 += p00 + p01;
      ps1 += p10 + p11;
      float2 w0 = {f2tf32(p00), f2tf32(p01)};
      float2 w1 = {f2tf32(p10), f2tf32(p11)};
      *(float2*)&Ps[myrow0 * PST + 8 * nt + 2 * tig] = w0;
      *(float2*)&Ps[myrow1 * PST + 8 * nt + 2 * tig] = w1;
    }
    ps0 += __shfl_xor_sync(0xffffffffu, ps0, 1);
    ps0 += __shfl_xor_sync(0xffffffffu, ps0, 2);
    ps1 += __shfl_xor_sync(0xffffffffu, ps1, 1);
    ps1 += __shfl_xor_sync(0xffffffffu, ps1, 2);
    l0 = l0 * c0 + ps0;
    l1 = l1 * c1 + ps1;
    m0r = nm0;
    m1r = nm1;
#pragma unroll
    for (int dt = 0; dt < 8; dt++) {
      o[dt][0] *= c0; o[dt][1] *= c0;
      o[dt][2] *= c1; o[dt][3] *= c1;
    }
    __syncwarp();

    const uint32_t* Psm = (const uint32_t*)Ps;
    const uint32_t* Vsm = (const uint32_t*)(VsA + buf * VBUF);
    uint32_t pa[8][4];
#pragma unroll
    for (int ks = 0; ks < 8; ks++) {
      const int kb = 8 * ks + tig;
      pa[ks][0] = Psm[myrow0 * PST + kb];
      pa[ks][1] = Psm[myrow1 * PST + kb];
      pa[ks][2] = Psm[myrow0 * PST + kb + 4];
      pa[ks][3] = Psm[myrow1 * PST + kb + 4];
    }
#pragma unroll
    for (int dt = 0; dt < 8; dt++) {
#pragma unroll
      for (int ks = 0; ks < 8; ks++) {
        const uint32_t b0 = Vsm[(8 * ks + tig) * VST + 8 * dt + g];
        const uint32_t b1 = Vsm[(8 * ks + tig + 4) * VST + 8 * dt + g];
        mma_tf32_2(o[dt], pa[ks], b0, b1);
      }
    }
  }

  // finalize: write Y in packed-A layout (global row = b*Tq + q, col = h*64+d)
  const float inv0 = 1.0f / l0;
  const float inv1 = 1.0f / l1;
  const int mr0 = b * Tq + q0 + myrow0;
  const int mr1 = b * Tq + q0 + myrow1;
#pragma unroll
  for (int dt = 0; dt < 8; dt++) {
    const int kc = h * 64 + 8 * dt + 2 * tig;
    g_Y[packA_idx(mr0, kc)]     = f2tf32(o[dt][0] * inv0);
    g_Y[packA_idx(mr0, kc + 1)] = f2tf32(o[dt][1] * inv0);
    g_Y[packA_idx(mr1, kc)]     = f2tf32(o[dt][2] * inv1);
    g_Y[packA_idx(mr1, kc + 1)] = f2tf32(o[dt][3] * inv1);
  }
}

// ---------------------------------------------------------------------------
extern "C" void kernel_launch(void* const* d_in, const int* in_sizes, int n_in,
                              void* d_out, int out_size) {
  const float* emb    = (const float*)d_in[0];
  const float* w_qkv  = (const float*)d_in[1];
  const float* b_qkv  = (const float*)d_in[2];
  const float* w_proj = (const float*)d_in[3];
  const float* b_proj = (const float*)d_in[4];
  float* out = (float*)d_out;

  static float* p_wqkvT = nullptr;
  static float* p_wprojT = nullptr;
  static float* p_Y = nullptr;
  static float* p_Atf = nullptr;
  static bool init_done = false;
  if (!init_done) {
    cudaGetSymbolAddress((void**)&p_wqkvT, g_WqkvT);
    cudaGetSymbolAddress((void**)&p_wprojT, g_WprojT);
    cudaGetSymbolAddress((void**)&p_Y, g_Y);
    cudaGetSymbolAddress((void**)&p_Atf, g_Atf);
    cudaFuncSetAttribute(flash_attn_tc_kernel,
                         cudaFuncAttributeMaxDynamicSharedMemorySize, ATTN_SMEM);
    init_done = true;
  }

  round_pack_kernel<<<Mq * Cq / 4 / 256, 256>>>(emb, p_Atf);
  transpose_pack_kernel<<<dim3(N_QKV / 32, Cq / 32), dim3(32, 8)>>>(w_qkv, p_wqkvT, N_QKV);
  transpose_pack_kernel<<<dim3(Cq / 32, Cq / 32), dim3(32, 8)>>>(w_proj, p_wprojT, Cq);

  // QKV: 128x256 tiles -> grid (3072/256, 18432/128)
  tc_gemm_kernel<0><<<dim3(N_QKV / 256, Mq / 128), 512>>>(
      p_Atf, p_wqkvT, b_qkv, nullptr);

  flash_attn_tc_kernel<<<dim3(Bq * Hq, Tq / QT), 128, ATTN_SMEM>>>();

  // proj: 128x256 tiles -> grid (1024/256, 18432/128)
  tc_gemm_kernel<1><<<dim3(Cq / 256, Mq / 128), 512>>>(
      p_Y, p_wprojT, b_proj, out);
}

// round 16
// speedup vs baseline: 1.1835x; 1.1835x over previous
#include <cuda_runtime.h>
#include <cuda_bf16.h>
#include <cstdint>

// Problem constants
#define Bq 32
#define Tq 576
#define Cq 1024
#define Hq 16
#define Dq 64
#define Mq (Bq * Tq)          // 18432
#define N_QKV (3 * Cq)        // 3072
#define NQT 9                 // Tq / 64

// Scratch (device globals; no allocation allowed)
__device__ float g_Q[(size_t)Bq * Hq * Tq * Dq];   // [B,H,T,D], tf32-rounded
__device__ float g_K[(size_t)Bq * Hq * Tq * Dq];
__device__ float g_V[(size_t)Bq * Hq * Tq * Dq];
__device__ float g_Y[(size_t)Mq * Cq];             // attention out, PACKED-A layout
__device__ float g_Atf[(size_t)Mq * Cq];           // emb tf32, PACKED-A layout
__device__ float g_WqkvT[(size_t)N_QKV * Cq];      // PACKED-B layout
__device__ float g_WprojT[(size_t)Cq * Cq];        // PACKED-B layout

// ---------------------------------------------------------------------------
// Fragment-packed layouts (K = 1024 -> 32 k-blocks of 32); see round 9.
// ---------------------------------------------------------------------------
__device__ __forceinline__ size_t packA_idx(int m, int k) {
  const int mblk = m >> 7, kblk = k >> 5;
  const int mt = (m >> 4) & 7, ks = (k >> 3) & 3;
  const int g = m & 7, mh = (m >> 3) & 1;
  const int tig = k & 3, kh = (k >> 2) & 1;
  return ((((size_t)(mblk * 32 + kblk) * 8 + mt) * 4 + ks) * 32 + (g * 4 + tig)) * 4
         + (mh + 2 * kh);
}

__device__ __forceinline__ size_t packB_idx(int n, int k) {
  const int nblk = n >> 7, kblk = k >> 5;
  const int nt = (n >> 3) & 15, ks = (k >> 3) & 3;
  const int g = n & 7;
  const int tig = k & 3, kh = (k >> 2) & 1;
  return ((((size_t)(nblk * 32 + kblk) * 16 + nt) * 4 + ks) * 32 + (g * 4 + tig)) * 2
         + kh;
}

// ---------------------------------------------------------------------------
__device__ __forceinline__ float f2tf32(float x) {
  uint32_t r;
  asm("cvt.rna.tf32.f32 %0, %1;" : "=r"(r) : "f"(x));
  return __uint_as_float(r);
}

__device__ __forceinline__ void cp_async16(uint32_t saddr, const void* gaddr) {
  asm volatile("cp.async.cg.shared.global [%0], [%1], 16;" :: "r"(saddr), "l"(gaddr));
}
#define CP_COMMIT() asm volatile("cp.async.commit_group;" ::: "memory")
#define CP_WAIT(n)  asm volatile("cp.async.wait_group %0;" :: "n"(n) : "memory")

__device__ __forceinline__ uint32_t smem_u32(const void* p) {
  uint32_t a;
  asm("{ .reg .u64 t; cvta.to.shared.u64 t, %1; cvt.u32.u64 %0, t; }"
      : "=r"(a) : "l"(p));
  return a;
}

__device__ __forceinline__ void prefetch_l1(const void* p) {
  asm volatile("prefetch.global.L1 [%0];" :: "l"(p));
}

__device__ __forceinline__ void mma_tf32(float* c, const uint32_t* a, const uint32_t* b) {
  asm volatile(
      "mma.sync.aligned.m16n8k8.row.col.f32.tf32.tf32.f32 "
      "{%0,%1,%2,%3}, {%4,%5,%6,%7}, {%8,%9}, {%0,%1,%2,%3};"
      : "+f"(c[0]), "+f"(c[1]), "+f"(c[2]), "+f"(c[3])
      : "r"(a[0]), "r"(a[1]), "r"(a[2]), "r"(a[3]), "r"(b[0]), "r"(b[1]));
}

__device__ __forceinline__ void mma_tf32_2(float* c, const uint32_t* a,
                                           uint32_t b0, uint32_t b1) {
  asm volatile(
      "mma.sync.aligned.m16n8k8.row.col.f32.tf32.tf32.f32 "
      "{%0,%1,%2,%3}, {%4,%5,%6,%7}, {%8,%9}, {%0,%1,%2,%3};"
      : "+f"(c[0]), "+f"(c[1]), "+f"(c[2]), "+f"(c[3])
      : "r"(a[0]), "r"(a[1]), "r"(a[2]), "r"(a[3]), "r"(b0), "r"(b1));
}

// ---------------------------------------------------------------------------
// emb -> tf32-rounded, packed-A layout
// ---------------------------------------------------------------------------
__global__ __launch_bounds__(256) void round_pack_kernel(const float* __restrict__ src,
                                                         float* __restrict__ dst) {
  const int i = blockIdx.x * 256 + threadIdx.x;
  if (i < Mq * Cq / 4) {
    const int m = (i * 4) / Cq;
    const int k = (i * 4) % Cq;
    const float4 v = ((const float4*)src)[i];
    dst[packA_idx(m, k + 0)] = f2tf32(v.x);
    dst[packA_idx(m, k + 1)] = f2tf32(v.y);
    dst[packA_idx(m, k + 2)] = f2tf32(v.z);
    dst[packA_idx(m, k + 3)] = f2tf32(v.w);
  }
}

// ---------------------------------------------------------------------------
// Weight transpose + tf32 + packed-B
// ---------------------------------------------------------------------------
__global__ __launch_bounds__(256) void transpose_pack_kernel(
    const float* __restrict__ src, float* __restrict__ dst, int C) {
  __shared__ float t[32][33];
  const int c0 = blockIdx.x * 32, r0 = blockIdx.y * 32;
  const int x = threadIdx.x, y = threadIdx.y;   // 32 x 8
#pragma unroll
  for (int i = 0; i < 32; i += 8)
    t[y + i][x] = src[(size_t)(r0 + y + i) * C + c0 + x];
  __syncthreads();
#pragma unroll
  for (int i = 0; i < 32; i += 8)
    dst[packB_idx(c0 + y + i, r0 + x)] = f2tf32(t[x][y + i]);
}

// ---------------------------------------------------------------------------
// Round-11 GEMM (EXACT): barrier-free tf32 mma.sync on packed operands,
// CTA 128x128, 256 thr, register prefetch depth 1 + full-warp L1 prefetch
// depth 2. MODE 0: QKV scatter; MODE 1: plain store.
// ---------------------------------------------------------------------------
#define G_NK 32

#define LOADG(kt_, ks_, c_) do {                                               \
    _Pragma("unroll")                                                          \
    for (int mt_ = 0; mt_ < 4; mt_++)                                          \
      af[c_][mt_] = __ldg(Afw + (kt_) * 1024 + (mt_ * 4 + (ks_)) * 32);        \
    _Pragma("unroll")                                                          \
    for (int nt_ = 0; nt_ < 4; nt_++)                                          \
      bf[c_][nt_] = __ldg(Bfw + (kt_) * 2048 + (nt_ * 4 + (ks_)) * 32);        \
  } while (0)

#define PREFG(kt_, ks_) do {                                                   \
    _Pragma("unroll")                                                          \
    for (int mt_ = 0; mt_ < 4; mt_++)                                          \
      prefetch_l1(Afw + (kt_) * 1024 + (mt_ * 4 + (ks_)) * 32);                \
    _Pragma("unroll")                                                          \
    for (int nt_ = 0; nt_ < 4; nt_++)                                          \
      prefetch_l1(Bfw + (kt_) * 2048 + (nt_ * 4 + (ks_)) * 32);                \
  } while (0)

template <int MODE>
__global__ __launch_bounds__(256, 2) void tc_gemm_kernel(
    const float* __restrict__ A, const float* __restrict__ BT,
    const float* __restrict__ bias, float* __restrict__ Out) {
  const int tid = threadIdx.x;
  const int wid = tid >> 5;
  const int lid = tid & 31;
  const int mblk = blockIdx.y;
  const int nblk = blockIdx.x;
  const int m0 = mblk * 128;
  const int n0 = nblk * 128;
  const int warp_m = wid & 1;
  const int warp_n = wid >> 1;
  const int g = lid >> 2, tig = lid & 3;

  const float4* Afw = (const float4*)A + (size_t)mblk * 32768 + warp_m * 512 + lid;
  const float2* Bfw = (const float2*)BT + (size_t)nblk * 65536 + warp_n * 512 + lid;

  float acc[4][4][4];
#pragma unroll
  for (int i = 0; i < 4; i++)
#pragma unroll
    for (int j = 0; j < 4; j++)
#pragma unroll
      for (int q = 0; q < 4; q++) acc[i][j][q] = 0.f;

  float4 af[2][4];
  float2 bf[2][4];

  LOADG(0, 0, 0);
  PREFG(0, 1);
  for (int kt = 0; kt < G_NK; kt++) {
#pragma unroll
    for (int ks = 0; ks < 4; ks++) {
      const int step = kt * 4 + ks;
      const int c = step & 1;
      const int nstep = step + 1;
      if (nstep < G_NK * 4) LOADG(nstep >> 2, nstep & 3, c ^ 1);
      const int pstep = step + 2;
      if (pstep < G_NK * 4) PREFG(pstep >> 2, pstep & 3);
#pragma unroll
      for (int mt = 0; mt < 4; mt++)
#pragma unroll
        for (int nt = 0; nt < 4; nt++)
          mma_tf32(acc[mt][nt], (const uint32_t*)&af[c][mt],
                   (const uint32_t*)&bf[c][nt]);
    }
  }

#pragma unroll
  for (int mt = 0; mt < 4; mt++) {
    const int row0 = m0 + warp_m * 64 + mt * 16 + g;
#pragma unroll
    for (int half = 0; half < 2; half++) {
      const int m = row0 + half * 8;
      const int bb = m / Tq;
      const int t = m % Tq;
#pragma unroll
      for (int nt = 0; nt < 4; nt++) {
        const int n = n0 + warp_n * 32 + nt * 8 + tig * 2;
        const float2 bv = *(const float2*)&bias[n];
        float2 o;
        o.x = acc[mt][nt][half * 2 + 0] + bv.x;
        o.y = acc[mt][nt][half * 2 + 1] + bv.y;
        if (MODE == 0) {
          o.x = f2tf32(o.x);
          o.y = f2tf32(o.y);
          const int which = n >> 10;
          const int ccn = n & 1023;
          const int h = ccn >> 6;
          const int d = ccn & 63;
          float* dst = (which == 0) ? g_Q : (which == 1) ? g_K : g_V;
          *(float2*)(dst + ((size_t)(bb * Hq + h) * Tq + t) * Dq + d) = o;
        } else {
          *(float2*)(Out + (size_t)m * Cq + n) = o;
        }
      }
    }
  }
}

// ---------------------------------------------------------------------------
// Paired tensor-core causal flash attention: one 256-thread block handles TWO
// adjacent 64-query tiles (2qp, 2qp+1), sharing the K/V smem pipeline.
// Warps 0-3 own the lower tile, warps 4-7 the upper. Causal mask is a global
// compare kg <= qg (fully-masked tiles contribute exactly 0). qp=4 is a
// singleton: upper warps mirror the lower tile with stores disabled.
// ---------------------------------------------------------------------------
#define QT 64
#define KST 68
#define VST 72
#define PST 68
#define KBUF (64 * KST)
#define VBUF (64 * VST)
#define ATTN_SMEM ((2 * KBUF + 2 * VBUF + 128 * PST) * 4)   // 106496 B

__device__ __forceinline__ void attn_prefetch2(const float* Kg, const float* Vg,
                                               float* Ksb, float* Vsb, int tid) {
#pragma unroll
  for (int i = 0; i < 4; i++) {
    const int c = tid + i * 256;     // 0..1023
    const int r = c >> 4;
    const int c4 = (c & 15) * 4;
    cp_async16(smem_u32(Ksb + r * KST + c4), Kg + (size_t)r * Dq + c4);
    cp_async16(smem_u32(Vsb + r * VST + c4), Vg + (size_t)r * Dq + c4);
  }
  CP_COMMIT();
}

__global__ __launch_bounds__(256) void flash_attn_tc2_kernel() {
  const int bh = blockIdx.x;            // 0..511
  const int qp = blockIdx.y;            // 0..4 (pair index)
  const int b = bh / Hq;
  const int h = bh % Hq;
  const int qt0 = 2 * qp;
  const bool has_hi = (qt0 + 1) < NQT;
  const int nkt = has_hi ? (qt0 + 2) : (qt0 + 1);

  const float* Qb = g_Q + (size_t)bh * Tq * Dq;
  const float* Kb = g_K + (size_t)bh * Tq * Dq;
  const float* Vb = g_V + (size_t)bh * Tq * Dq;

  extern __shared__ float smf[];
  float* KsA = smf;                       // [2][64][KST]
  float* VsA = smf + 2 * KBUF;            // [2][64][VST]
  float* Ps  = smf + 2 * KBUF + 2 * VBUF; // [128][PST]

  const int tid = threadIdx.x;
  const int wid = tid >> 5;               // 0..7
  const int lid = tid & 31;
  const int g = lid >> 2;
  const int tig = lid & 3;
  const int half_id = wid >> 2;           // 0 = lower tile, 1 = upper
  const int wq = wid & 3;
  const bool mine = (half_id == 0) || has_hi;
  const int myqt = (half_id && has_hi) ? (qt0 + 1) : qt0;
  const int tile_off = (half_id && has_hi) ? 64 : 0;   // Ps row base
  const int lr0 = 16 * wq + g;
  const int lr1 = lr0 + 8;
  const int qg0 = myqt * QT + lr0;        // global query rows
  const int qg1 = myqt * QT + lr1;
  const int q0 = qt0 * QT;

  // Prefetch K/V tile 0
  attn_prefetch2(Kb, Vb, KsA, VsA, tid);

  // Stage 128 rows of Q (two tiles; rows past Tq clamped, values unused)
#pragma unroll
  for (int i = 0; i < 8; i++) {
    const int c = tid + i * 256;          // 0..2047
    const int r = c >> 4;                 // 0..127
    const int c4 = (c & 15) * 4;
    int qrow = q0 + r;
    if (qrow > Tq - 1) qrow = Tq - 1;
    const float4 v = *(const float4*)&Qb[(size_t)qrow * Dq + c4];
    float* dr = &Ps[r * PST + c4];
    dr[0] = v.x; dr[1] = v.y; dr[2] = v.z; dr[3] = v.w;
  }
  __syncthreads();

  uint32_t qa[8][4];
  {
    const uint32_t* Qsm = (const uint32_t*)Ps;
    const int r0 = tile_off + lr0;
#pragma unroll
    for (int ks = 0; ks < 8; ks++) {
      const int kb = 8 * ks + tig;
      qa[ks][0] = Qsm[r0 * PST + kb];
      qa[ks][1] = Qsm[(r0 + 8) * PST + kb];
      qa[ks][2] = Qsm[r0 * PST + kb + 4];
      qa[ks][3] = Qsm[(r0 + 8) * PST + kb + 4];
    }
  }

  float o[8][4];
#pragma unroll
  for (int i = 0; i < 8; i++)
#pragma unroll
    for (int j = 0; j < 4; j++) o[i][j] = 0.f;
  float m0r = -1e30f, m1r = -1e30f, l0 = 0.f, l1 = 0.f;
  const float scale = 1.0f / 64.0f;
  const int pr0 = tile_off + lr0;         // Ps rows for P
  const int pr1 = tile_off + lr1;

  for (int kt = 0; kt < nkt; kt++) {
    const int buf = kt & 1;
    __syncthreads();   // prev buffer consumers done; Q staging/extraction done
    if (kt + 1 < nkt) {
      attn_prefetch2(Kb + (size_t)(kt + 1) * 64 * Dq, Vb + (size_t)(kt + 1) * 64 * Dq,
                     KsA + (buf ^ 1) * KBUF, VsA + (buf ^ 1) * VBUF, tid);
      CP_WAIT(1);
    } else {
      CP_WAIT(0);
    }
    __syncthreads();

    // ---- S = Q @ K^T ----
    const uint32_t* Ksm = (const uint32_t*)(KsA + buf * KBUF);
    float s[8][4];
#pragma unroll
    for (int nt = 0; nt < 8; nt++) {
      s[nt][0] = s[nt][1] = s[nt][2] = s[nt][3] = 0.f;
      const uint32_t* kr = Ksm + (8 * nt + g) * KST;
#pragma unroll
      for (int ks = 0; ks < 8; ks++) {
        const int kb = 8 * ks + tig;
        mma_tf32_2(s[nt], qa[ks], kr[kb], kr[kb + 4]);
      }
    }

    // ---- scale + causal mask (global compare) + row max ----
    float mx0 = -1e30f, mx1 = -1e30f;
#pragma unroll
    for (int nt = 0; nt < 8; nt++) {
#pragma unroll
      for (int ccx = 0; ccx < 2; ccx++) {
        const int kg = kt * 64 + 8 * nt + 2 * tig + ccx;
        s[nt][ccx]     = (kg <= qg0) ? s[nt][ccx] * scale     : -1e30f;
        s[nt][2 + ccx] = (kg <= qg1) ? s[nt][2 + ccx] * scale : -1e30f;
        mx0 = fmaxf(mx0, s[nt][ccx]);
        mx1 = fmaxf(mx1, s[nt][2 + ccx]);
      }
    }
    mx0 = fmaxf(mx0, __shfl_xor_sync(0xffffffffu, mx0, 1));
    mx0 = fmaxf(mx0, __shfl_xor_sync(0xffffffffu, mx0, 2));
    mx1 = fmaxf(mx1, __shfl_xor_sync(0xffffffffu, mx1, 1));
    mx1 = fmaxf(mx1, __shfl_xor_sync(0xffffffffu, mx1, 2));

    const float nm0 = fmaxf(m0r, mx0);
    const float nm1 = fmaxf(m1r, mx1);
    const float c0 = __expf(m0r - nm0);
    const float c1 = __expf(m1r - nm1);

    float ps0 = 0.f, ps1 = 0.f;
#pragma unroll
    for (int nt = 0; nt < 8; nt++) {
      const float p00 = __expf(s[nt][0] - nm0);
      const float p01 = __expf(s[nt][1] - nm0);
      const float p10 = __expf(s[nt][2] - nm1);
      const float p11 = __expf(s[nt][3] - nm1);
      ps0 += p00 + p01;
      ps1 += p10 + p11;
      float2 w0 = {f2tf32(p00), f2tf32(p01)};
      float2 w1 = {f2tf32(p10), f2tf32(p11)};
      *(float2*)&Ps[pr0 * PST + 8 * nt + 2 * tig] = w0;
      *(float2*)&Ps[pr1 * PST + 8 * nt + 2 * tig] = w1;
    }
    ps0 += __shfl_xor_sync(0xffffffffu, ps0, 1);
    ps0 += __shfl_xor_sync(0xffffffffu, ps0, 2);
    ps1 += __shfl_xor_sync(0xffffffffu, ps1, 1);
    ps1 += __shfl_xor_sync(0xffffffffu, ps1, 2);
    l0 = l0 * c0 + ps0;
    l1 = l1 * c1 + ps1;
    m0r = nm0;
    m1r = nm1;
#pragma unroll
    for (int dt = 0; dt < 8; dt++) {
      o[dt][0] *= c0; o[dt][1] *= c0;
      o[dt][2] *= c1; o[dt][3] *= c1;
    }
    __syncwarp();   // P rows are warp-private (or identical-valued duplicates)

    // ---- O += P @ V ----
    const uint32_t* Psm = (const uint32_t*)Ps;
    const uint32_t* Vsm = (const uint32_t*)(VsA + buf * VBUF);
    uint32_t pa[8][4];
#pragma unroll
    for (int ks = 0; ks < 8; ks++) {
      const int kb = 8 * ks + tig;
      pa[ks][0] = Psm[pr0 * PST + kb];
      pa[ks][1] = Psm[pr1 * PST + kb];
      pa[ks][2] = Psm[pr0 * PST + kb + 4];
      pa[ks][3] = Psm[pr1 * PST + kb + 4];
    }
#pragma unroll
    for (int dt = 0; dt < 8; dt++) {
#pragma unroll
      for (int ks = 0; ks < 8; ks++) {
        const uint32_t b0 = Vsm[(8 * ks + tig) * VST + 8 * dt + g];
        const uint32_t b1 = Vsm[(8 * ks + tig + 4) * VST + 8 * dt + g];
        mma_tf32_2(o[dt], pa[ks], b0, b1);
      }
    }
  }

  // ---- finalize: write Y in packed-A layout (skip mirrored upper warps) ----
  if (mine) {
    const float inv0 = 1.0f / l0;
    const float inv1 = 1.0f / l1;
    const int mr0 = b * Tq + qg0;
    const int mr1 = b * Tq + qg1;
#pragma unroll
    for (int dt = 0; dt < 8; dt++) {
      const int kc = h * 64 + 8 * dt + 2 * tig;
      g_Y[packA_idx(mr0, kc)]     = f2tf32(o[dt][0] * inv0);
      g_Y[packA_idx(mr0, kc + 1)] = f2tf32(o[dt][1] * inv0);
      g_Y[packA_idx(mr1, kc)]     = f2tf32(o[dt][2] * inv1);
      g_Y[packA_idx(mr1, kc + 1)] = f2tf32(o[dt][3] * inv1);
    }
  }
}

// ---------------------------------------------------------------------------
extern "C" void kernel_launch(void* const* d_in, const int* in_sizes, int n_in,
                              void* d_out, int out_size) {
  const float* emb    = (const float*)d_in[0];
  const float* w_qkv  = (const float*)d_in[1];
  const float* b_qkv  = (const float*)d_in[2];
  const float* w_proj = (const float*)d_in[3];
  const float* b_proj = (const float*)d_in[4];
  float* out = (float*)d_out;

  static float* p_wqkvT = nullptr;
  static float* p_wprojT = nullptr;
  static float* p_Y = nullptr;
  static float* p_Atf = nullptr;
  static bool init_done = false;
  if (!init_done) {
    cudaGetSymbolAddress((void**)&p_wqkvT, g_WqkvT);
    cudaGetSymbolAddress((void**)&p_wprojT, g_WprojT);
    cudaGetSymbolAddress((void**)&p_Y, g_Y);
    cudaGetSymbolAddress((void**)&p_Atf, g_Atf);
    cudaFuncSetAttribute(flash_attn_tc2_kernel,
                         cudaFuncAttributeMaxDynamicSharedMemorySize, ATTN_SMEM);
    init_done = true;
  }

  round_pack_kernel<<<Mq * Cq / 4 / 256, 256>>>(emb, p_Atf);
  transpose_pack_kernel<<<dim3(N_QKV / 32, Cq / 32), dim3(32, 8)>>>(w_qkv, p_wqkvT, N_QKV);
  transpose_pack_kernel<<<dim3(Cq / 32, Cq / 32), dim3(32, 8)>>>(w_proj, p_wprojT, Cq);

  tc_gemm_kernel<0><<<dim3(N_QKV / 128, Mq / 128), 256>>>(
      p_Atf, p_wqkvT, b_qkv, nullptr);

  flash_attn_tc2_kernel<<<dim3(Bq * Hq, (NQT + 1) / 2), 256, ATTN_SMEM>>>();

  tc_gemm_kernel<1><<<dim3(Cq / 128, Mq / 128), 256>>>(
      p_Y, p_wprojT, b_proj, out);
}

// round 17
// speedup vs baseline: 1.3095x; 1.1065x over previous
#include <cuda_runtime.h>
#include <cuda_bf16.h>
#include <cstdint>

// Problem constants
#define Bq 32
#define Tq 576
#define Cq 1024
#define Hq 16
#define Dq 64
#define Mq (Bq * Tq)          // 18432
#define N_QKV (3 * Cq)        // 3072

// Scratch (device globals; no allocation allowed)
__device__ float g_Q[(size_t)Bq * Hq * Tq * Dq];   // [B,H,T,D], tf32-rounded
__device__ float g_K[(size_t)Bq * Hq * Tq * Dq];
__device__ float g_V[(size_t)Bq * Hq * Tq * Dq];
__device__ float g_Y[(size_t)Mq * Cq];             // attention out, PACKED-A layout
__device__ float g_Atf[(size_t)Mq * Cq];           // emb tf32, PACKED-A layout
__device__ float g_WqkvT[(size_t)N_QKV * Cq];      // PACKED-B layout
__device__ float g_WprojT[(size_t)Cq * Cq];        // PACKED-B layout

// ---------------------------------------------------------------------------
// Fragment-packed layouts (K = 1024 -> 32 k-blocks of 32); see round 9.
// ---------------------------------------------------------------------------
__device__ __forceinline__ size_t packA_idx(int m, int k) {
  const int mblk = m >> 7, kblk = k >> 5;
  const int mt = (m >> 4) & 7, ks = (k >> 3) & 3;
  const int g = m & 7, mh = (m >> 3) & 1;
  const int tig = k & 3, kh = (k >> 2) & 1;
  return ((((size_t)(mblk * 32 + kblk) * 8 + mt) * 4 + ks) * 32 + (g * 4 + tig)) * 4
         + (mh + 2 * kh);
}

__device__ __forceinline__ size_t packB_idx(int n, int k) {
  const int nblk = n >> 7, kblk = k >> 5;
  const int nt = (n >> 3) & 15, ks = (k >> 3) & 3;
  const int g = n & 7;
  const int tig = k & 3, kh = (k >> 2) & 1;
  return ((((size_t)(nblk * 32 + kblk) * 16 + nt) * 4 + ks) * 32 + (g * 4 + tig)) * 2
         + kh;
}

// ---------------------------------------------------------------------------
__device__ __forceinline__ float f2tf32(float x) {
  uint32_t r;
  asm("cvt.rna.tf32.f32 %0, %1;" : "=r"(r) : "f"(x));
  return __uint_as_float(r);
}

__device__ __forceinline__ void cp_async16(uint32_t saddr, const void* gaddr) {
  asm volatile("cp.async.cg.shared.global [%0], [%1], 16;" :: "r"(saddr), "l"(gaddr));
}
#define CP_COMMIT() asm volatile("cp.async.commit_group;" ::: "memory")
#define CP_WAIT(n)  asm volatile("cp.async.wait_group %0;" :: "n"(n) : "memory")

__device__ __forceinline__ uint32_t smem_u32(const void* p) {
  uint32_t a;
  asm("{ .reg .u64 t; cvta.to.shared.u64 t, %1; cvt.u32.u64 %0, t; }"
      : "=r"(a) : "l"(p));
  return a;
}

__device__ __forceinline__ void prefetch_l1(const void* p) {
  asm volatile("prefetch.global.L1 [%0];" :: "l"(p));
}

__device__ __forceinline__ void mma_tf32(float* c, const uint32_t* a, const uint32_t* b) {
  asm volatile(
      "mma.sync.aligned.m16n8k8.row.col.f32.tf32.tf32.f32 "
      "{%0,%1,%2,%3}, {%4,%5,%6,%7}, {%8,%9}, {%0,%1,%2,%3};"
      : "+f"(c[0]), "+f"(c[1]), "+f"(c[2]), "+f"(c[3])
      : "r"(a[0]), "r"(a[1]), "r"(a[2]), "r"(a[3]), "r"(b[0]), "r"(b[1]));
}

__device__ __forceinline__ void mma_tf32_2(float* c, const uint32_t* a,
                                           uint32_t b0, uint32_t b1) {
  asm volatile(
      "mma.sync.aligned.m16n8k8.row.col.f32.tf32.tf32.f32 "
      "{%0,%1,%2,%3}, {%4,%5,%6,%7}, {%8,%9}, {%0,%1,%2,%3};"
      : "+f"(c[0]), "+f"(c[1]), "+f"(c[2]), "+f"(c[3])
      : "r"(a[0]), "r"(a[1]), "r"(a[2]), "r"(a[3]), "r"(b0), "r"(b1));
}

// ---------------------------------------------------------------------------
// emb -> tf32-rounded, packed-A layout
// ---------------------------------------------------------------------------
__global__ __launch_bounds__(256) void round_pack_kernel(const float* __restrict__ src,
                                                         float* __restrict__ dst) {
  const int i = blockIdx.x * 256 + threadIdx.x;
  if (i < Mq * Cq / 4) {
    const int m = (i * 4) / Cq;
    const int k = (i * 4) % Cq;
    const float4 v = ((const float4*)src)[i];
    dst[packA_idx(m, k + 0)] = f2tf32(v.x);
    dst[packA_idx(m, k + 1)] = f2tf32(v.y);
    dst[packA_idx(m, k + 2)] = f2tf32(v.z);
    dst[packA_idx(m, k + 3)] = f2tf32(v.w);
  }
}

// ---------------------------------------------------------------------------
// Weight transpose + tf32 + packed-B
// ---------------------------------------------------------------------------
__global__ __launch_bounds__(256) void transpose_pack_kernel(
    const float* __restrict__ src, float* __restrict__ dst, int C) {
  __shared__ float t[32][33];
  const int c0 = blockIdx.x * 32, r0 = blockIdx.y * 32;
  const int x = threadIdx.x, y = threadIdx.y;   // 32 x 8
#pragma unroll
  for (int i = 0; i < 32; i += 8)
    t[y + i][x] = src[(size_t)(r0 + y + i) * C + c0 + x];
  __syncthreads();
#pragma unroll
  for (int i = 0; i < 32; i += 8)
    dst[packB_idx(c0 + y + i, r0 + x)] = f2tf32(t[x][y + i]);
}

// ---------------------------------------------------------------------------
// Round-11 GEMM (EXACT): barrier-free tf32 mma.sync on packed operands,
// CTA 128x128, 256 thr, register prefetch depth 1 + full-warp L1 prefetch
// depth 2. MODE 0: QKV scatter; MODE 1: plain store.
// ---------------------------------------------------------------------------
#define G_NK 32

#define LOADG(kt_, ks_, c_) do {                                               \
    _Pragma("unroll")                                                          \
    for (int mt_ = 0; mt_ < 4; mt_++)                                          \
      af[c_][mt_] = __ldg(Afw + (kt_) * 1024 + (mt_ * 4 + (ks_)) * 32);        \
    _Pragma("unroll")                                                          \
    for (int nt_ = 0; nt_ < 4; nt_++)                                          \
      bf[c_][nt_] = __ldg(Bfw + (kt_) * 2048 + (nt_ * 4 + (ks_)) * 32);        \
  } while (0)

#define PREFG(kt_, ks_) do {                                                   \
    _Pragma("unroll")                                                          \
    for (int mt_ = 0; mt_ < 4; mt_++)                                          \
      prefetch_l1(Afw + (kt_) * 1024 + (mt_ * 4 + (ks_)) * 32);                \
    _Pragma("unroll")                                                          \
    for (int nt_ = 0; nt_ < 4; nt_++)                                          \
      prefetch_l1(Bfw + (kt_) * 2048 + (nt_ * 4 + (ks_)) * 32);                \
  } while (0)

template <int MODE>
__global__ __launch_bounds__(256, 2) void tc_gemm_kernel(
    const float* __restrict__ A, const float* __restrict__ BT,
    const float* __restrict__ bias, float* __restrict__ Out) {
  const int tid = threadIdx.x;
  const int wid = tid >> 5;
  const int lid = tid & 31;
  const int mblk = blockIdx.y;
  const int nblk = blockIdx.x;
  const int m0 = mblk * 128;
  const int n0 = nblk * 128;
  const int warp_m = wid & 1;
  const int warp_n = wid >> 1;
  const int g = lid >> 2, tig = lid & 3;

  const float4* Afw = (const float4*)A + (size_t)mblk * 32768 + warp_m * 512 + lid;
  const float2* Bfw = (const float2*)BT + (size_t)nblk * 65536 + warp_n * 512 + lid;

  float acc[4][4][4];
#pragma unroll
  for (int i = 0; i < 4; i++)
#pragma unroll
    for (int j = 0; j < 4; j++)
#pragma unroll
      for (int q = 0; q < 4; q++) acc[i][j][q] = 0.f;

  float4 af[2][4];
  float2 bf[2][4];

  LOADG(0, 0, 0);
  PREFG(0, 1);
  for (int kt = 0; kt < G_NK; kt++) {
#pragma unroll
    for (int ks = 0; ks < 4; ks++) {
      const int step = kt * 4 + ks;
      const int c = step & 1;
      const int nstep = step + 1;
      if (nstep < G_NK * 4) LOADG(nstep >> 2, nstep & 3, c ^ 1);
      const int pstep = step + 2;
      if (pstep < G_NK * 4) PREFG(pstep >> 2, pstep & 3);
#pragma unroll
      for (int mt = 0; mt < 4; mt++)
#pragma unroll
        for (int nt = 0; nt < 4; nt++)
          mma_tf32(acc[mt][nt], (const uint32_t*)&af[c][mt],
                   (const uint32_t*)&bf[c][nt]);
    }
  }

#pragma unroll
  for (int mt = 0; mt < 4; mt++) {
    const int row0 = m0 + warp_m * 64 + mt * 16 + g;
#pragma unroll
    for (int half = 0; half < 2; half++) {
      const int m = row0 + half * 8;
      const int bb = m / Tq;
      const int t = m % Tq;
#pragma unroll
      for (int nt = 0; nt < 4; nt++) {
        const int n = n0 + warp_n * 32 + nt * 8 + tig * 2;
        const float2 bv = *(const float2*)&bias[n];
        float2 o;
        o.x = acc[mt][nt][half * 2 + 0] + bv.x;
        o.y = acc[mt][nt][half * 2 + 1] + bv.y;
        if (MODE == 0) {
          o.x = f2tf32(o.x);
          o.y = f2tf32(o.y);
          const int which = n >> 10;
          const int ccn = n & 1023;
          const int h = ccn >> 6;
          const int d = ccn & 63;
          float* dst = (which == 0) ? g_Q : (which == 1) ? g_K : g_V;
          *(float2*)(dst + ((size_t)(bb * Hq + h) * Tq + t) * Dq + d) = o;
        } else {
          *(float2*)(Out + (size_t)m * Cq + n) = o;
        }
      }
    }
  }
}

// ---------------------------------------------------------------------------
// Tensor-core causal flash attention (round-5 math), SINGLE-buffered K/V:
// smem 53.2 KB -> 4 CTAs/SM (vs 2), so barrier/latency bubbles overlap across
// independent CTAs. 128 threads / 4 warps, one 64-query tile per block.
// ---------------------------------------------------------------------------
#define QT 64
#define KST 68
#define VST 72
#define PST 68
#define KBUF (64 * KST)
#define VBUF (64 * VST)
#define ATTN_SMEM ((KBUF + VBUF + 64 * PST) * 4)   // 53248 B

__device__ __forceinline__ void attn_prefetch(const float* Kg, const float* Vg,
                                              float* Ksb, float* Vsb, int tid) {
#pragma unroll
  for (int i = 0; i < 8; i++) {
    const int c = tid + i * 128;
    const int r = c >> 4;
    const int c4 = (c & 15) * 4;
    cp_async16(smem_u32(Ksb + r * KST + c4), Kg + (size_t)r * Dq + c4);
    cp_async16(smem_u32(Vsb + r * VST + c4), Vg + (size_t)r * Dq + c4);
  }
  CP_COMMIT();
}

__global__ __launch_bounds__(128, 4) void flash_attn_tc_kernel() {
  const int bh = blockIdx.x;
  const int qt = blockIdx.y;
  const int b = bh / Hq;
  const int h = bh % Hq;

  const float* Qb = g_Q + (size_t)bh * Tq * Dq;
  const float* Kb = g_K + (size_t)bh * Tq * Dq;
  const float* Vb = g_V + (size_t)bh * Tq * Dq;

  extern __shared__ float smf[];
  float* Ks = smf;                  // [64][KST]
  float* Vs = smf + KBUF;           // [64][VST]
  float* Ps = smf + KBUF + VBUF;    // [64][PST]

  const int tid = threadIdx.x;
  const int wid = tid >> 5;
  const int lid = tid & 31;
  const int g = lid >> 2;
  const int tig = lid & 3;
  const int q0 = qt * QT;
  const int nkt = qt + 1;

  // Load K/V tile 0 (async; consumed after the first wait+barrier below)
  attn_prefetch(Kb, Vb, Ks, Vs, tid);

  // Stage Q tile into Ps, extract persistent A fragments
#pragma unroll
  for (int i = 0; i < 8; i++) {
    const int c = tid + i * 128;
    const int r = c >> 4;
    const int c4 = (c & 15) * 4;
    const float4 v = *(const float4*)&Qb[(size_t)(q0 + r) * Dq + c4];
    float* dr = &Ps[r * PST + c4];
    dr[0] = v.x; dr[1] = v.y; dr[2] = v.z; dr[3] = v.w;
  }
  __syncthreads();

  uint32_t qa[8][4];
  {
    const uint32_t* Qsm = (const uint32_t*)Ps;
    const int r0 = 16 * wid + g;
#pragma unroll
    for (int ks = 0; ks < 8; ks++) {
      const int kb = 8 * ks + tig;
      qa[ks][0] = Qsm[r0 * PST + kb];
      qa[ks][1] = Qsm[(r0 + 8) * PST + kb];
      qa[ks][2] = Qsm[r0 * PST + kb + 4];
      qa[ks][3] = Qsm[(r0 + 8) * PST + kb + 4];
    }
  }

  float o[8][4];
#pragma unroll
  for (int i = 0; i < 8; i++)
#pragma unroll
    for (int j = 0; j < 4; j++) o[i][j] = 0.f;
  float m0r = -1e30f, m1r = -1e30f, l0 = 0.f, l1 = 0.f;
  const float scale = 1.0f / 64.0f;
  const int myrow0 = 16 * wid + g;
  const int myrow1 = myrow0 + 8;

  for (int kt = 0; kt < nkt; kt++) {
    if (kt) {
      __syncthreads();   // all warps done reading tile kt-1's K/V
      attn_prefetch(Kb + (size_t)kt * 64 * Dq, Vb + (size_t)kt * 64 * Dq,
                    Ks, Vs, tid);
    }
    CP_WAIT(0);
    __syncthreads();     // tile kt's K/V visible to all warps

    const uint32_t* Ksm = (const uint32_t*)Ks;
    float s[8][4];
#pragma unroll
    for (int nt = 0; nt < 8; nt++) {
      s[nt][0] = s[nt][1] = s[nt][2] = s[nt][3] = 0.f;
      const uint32_t* kr = Ksm + (8 * nt + g) * KST;
#pragma unroll
      for (int ks = 0; ks < 8; ks++) {
        const int kb = 8 * ks + tig;
        mma_tf32_2(s[nt], qa[ks], kr[kb], kr[kb + 4]);
      }
    }

    const bool diag = (kt == qt);
    float mx0 = -1e30f, mx1 = -1e30f;
#pragma unroll
    for (int nt = 0; nt < 8; nt++) {
#pragma unroll
      for (int ccx = 0; ccx < 2; ccx++) {
        const int kcol = 8 * nt + 2 * tig + ccx;
        const bool ok0 = !diag || (kcol <= myrow0);
        const bool ok1 = !diag || (kcol <= myrow1);
        s[nt][ccx]     = ok0 ? s[nt][ccx] * scale     : -1e30f;
        s[nt][2 + ccx] = ok1 ? s[nt][2 + ccx] * scale : -1e30f;
        mx0 = fmaxf(mx0, s[nt][ccx]);
        mx1 = fmaxf(mx1, s[nt][2 + ccx]);
      }
    }
    mx0 = fmaxf(mx0, __shfl_xor_sync(0xffffffffu, mx0, 1));
    mx0 = fmaxf(mx0, __shfl_xor_sync(0xffffffffu, mx0, 2));
    mx1 = fmaxf(mx1, __shfl_xor_sync(0xffffffffu, mx1, 1));
    mx1 = fmaxf(mx1, __shfl_xor_sync(0xffffffffu, mx1, 2));

    const float nm0 = fmaxf(m0r, mx0);
    const float nm1 = fmaxf(m1r, mx1);
    const float c0 = __expf(m0r - nm0);
    const float c1 = __expf(m1r - nm1);

    float ps0 = 0.f, ps1 = 0.f;
#pragma unroll
    for (int nt = 0; nt < 8; nt++) {
      const float p00 = __expf(s[nt][0] - nm0);
      const float p01 = __expf(s[nt][1] - nm0);
      const float p10 = __expf(s[nt][2] - nm1);
      const float p11 = __expf(s[nt][3] - nm1);
      ps0 += p00 + p01;
      ps1 += p10 + p11;
      float2 w0 = {f2tf32(p00), f2tf32(p01)};
      float2 w1 = {f2tf32(p10), f2tf32(p11)};
      *(float2*)&Ps[myrow0 * PST + 8 * nt + 2 * tig] = w0;
      *(float2*)&Ps[myrow1 * PST + 8 * nt + 2 * tig] = w1;
    }
    ps0 += __shfl_xor_sync(0xffffffffu, ps0, 1);
    ps0 += __shfl_xor_sync(0xffffffffu, ps0, 2);
    ps1 += __shfl_xor_sync(0xffffffffu, ps1, 1);
    ps1 += __shfl_xor_sync(0xffffffffu, ps1, 2);
    l0 = l0 * c0 + ps0;
    l1 = l1 * c1 + ps1;
    m0r = nm0;
    m1r = nm1;
#pragma unroll
    for (int dt = 0; dt < 8; dt++) {
      o[dt][0] *= c0; o[dt][1] *= c0;
      o[dt][2] *= c1; o[dt][3] *= c1;
    }
    __syncwarp();

    const uint32_t* Psm = (const uint32_t*)Ps;
    const uint32_t* Vsm = (const uint32_t*)Vs;
    uint32_t pa[8][4];
#pragma unroll
    for (int ks = 0; ks < 8; ks++) {
      const int kb = 8 * ks + tig;
      pa[ks][0] = Psm[myrow0 * PST + kb];
      pa[ks][1] = Psm[myrow1 * PST + kb];
      pa[ks][2] = Psm[myrow0 * PST + kb + 4];
      pa[ks][3] = Psm[myrow1 * PST + kb + 4];
    }
#pragma unroll
    for (int dt = 0; dt < 8; dt++) {
#pragma unroll
      for (int ks = 0; ks < 8; ks++) {
        const uint32_t b0 = Vsm[(8 * ks + tig) * VST + 8 * dt + g];
        const uint32_t b1 = Vsm[(8 * ks + tig + 4) * VST + 8 * dt + g];
        mma_tf32_2(o[dt], pa[ks], b0, b1);
      }
    }
  }

  // finalize: write Y in packed-A layout (global row = b*Tq + q, col = h*64+d)
  const float inv0 = 1.0f / l0;
  const float inv1 = 1.0f / l1;
  const int mr0 = b * Tq + q0 + myrow0;
  const int mr1 = b * Tq + q0 + myrow1;
#pragma unroll
  for (int dt = 0; dt < 8; dt++) {
    const int kc = h * 64 + 8 * dt + 2 * tig;
    g_Y[packA_idx(mr0, kc)]     = f2tf32(o[dt][0] * inv0);
    g_Y[packA_idx(mr0, kc + 1)] = f2tf32(o[dt][1] * inv0);
    g_Y[packA_idx(mr1, kc)]     = f2tf32(o[dt][2] * inv1);
    g_Y[packA_idx(mr1, kc + 1)] = f2tf32(o[dt][3] * inv1);
  }
}

// ---------------------------------------------------------------------------
extern "C" void kernel_launch(void* const* d_in, const int* in_sizes, int n_in,
                              void* d_out, int out_size) {
  const float* emb    = (const float*)d_in[0];
  const float* w_qkv  = (const float*)d_in[1];
  const float* b_qkv  = (const float*)d_in[2];
  const float* w_proj = (const float*)d_in[3];
  const float* b_proj = (const float*)d_in[4];
  float* out = (float*)d_out;

  static float* p_wqkvT = nullptr;
  static float* p_wprojT = nullptr;
  static float* p_Y = nullptr;
  static float* p_Atf = nullptr;
  static bool init_done = false;
  if (!init_done) {
    cudaGetSymbolAddress((void**)&p_wqkvT, g_WqkvT);
    cudaGetSymbolAddress((void**)&p_wprojT, g_WprojT);
    cudaGetSymbolAddress((void**)&p_Y, g_Y);
    cudaGetSymbolAddress((void**)&p_Atf, g_Atf);
    cudaFuncSetAttribute(flash_attn_tc_kernel,
                         cudaFuncAttributeMaxDynamicSharedMemorySize, ATTN_SMEM);
    init_done = true;
  }

  round_pack_kernel<<<Mq * Cq / 4 / 256, 256>>>(emb, p_Atf);
  transpose_pack_kernel<<<dim3(N_QKV / 32, Cq / 32), dim3(32, 8)>>>(w_qkv, p_wqkvT, N_QKV);
  transpose_pack_kernel<<<dim3(Cq / 32, Cq / 32), dim3(32, 8)>>>(w_proj, p_wprojT, Cq);

  tc_gemm_kernel<0><<<dim3(N_QKV / 128, Mq / 128), 256>>>(
      p_Atf, p_wqkvT, b_qkv, nullptr);

  flash_attn_tc_kernel<<<dim3(Bq * Hq, Tq / QT), 128, ATTN_SMEM>>>();

  tc_gemm_kernel<1><<<dim3(Cq / 128, Mq / 128), 256>>>(
      p_Y, p_wprojT, b_proj, out);
}